// round 14
// baseline (speedup 1.0000x reference)
#include <cuda_runtime.h>
#include <math.h>

#define BB   16
#define NN   2048
#define DD   128
#define NSL  8
#define HH   128
#define RWS  (BB*NSL)            // 128 slot rows
#define EPSV 1e-8f
#define CH2  32                  // n-rows per kP chunk
#define KSTR 33                  // float4 stride for ks rows

// ---------------- scratch (__device__ globals: allocation-free) ----------------
__device__ float g_k[BB*NN*DD];          // 16 MB, k == v
__device__ float g_mus[RWS*DD];          // mu_s (GRU hidden)
__device__ float g_wa[RWS*DD];           // inv_var
__device__ float g_wb[RWS*DD];           // -2*inv*qmu
__device__ float g_wc[RWS];              // sum inv*qmu^2
__device__ float g_pi[RWS];
__device__ float g_gsum[RWS];
__device__ float g_accV[RWS*DD];
__device__ float g_accV2[RWS*DD];

// transposed weights
__device__ float g_WqT[DD*DD];           // [c][d]
__device__ float g_WihT[DD*3*DD];        // [c][j]
__device__ float g_WhhT[DD*3*DD];
__device__ float g_W1muT[DD*HH];         // [c][j]
__device__ float g_W2muT[HH*DD];         // [j][d]
__device__ float g_W1oT[2*DD*2*HH];      // [c][j]
__device__ float g_W2oT[2*HH*DD];        // [c][d]

// ---------------- 8-warp block reduce ----------------
__device__ __forceinline__ float blkSum8(float v, float* red, int tid) {
  int lane = tid&31, w = tid>>5;
  #pragma unroll
  for (int o=16;o;o>>=1) v += __shfl_xor_sync(0xffffffffu,v,o);
  if (lane==0) red[w] = v;
  __syncthreads();
  float tot = red[0]+red[1]+red[2]+red[3]+red[4]+red[5]+red[6]+red[7];
  __syncthreads();
  return tot;
}

// ---------------- kFused: kA (blocks 0-511) + transposes (512-575)
//                  + slot-init/first-Q-phase (576-703); 256 threads ------------
__global__ void kFused(const float* __restrict__ inp,
                       const float* __restrict__ lng, const float* __restrict__ lnb,
                       const float* __restrict__ noise, const float* __restrict__ smu,
                       const float* __restrict__ slsig,
                       const float* __restrict__ lsg, const float* __restrict__ lsb,
                       const float* __restrict__ Wq, const float* __restrict__ Wk,
                       const float* __restrict__ Wih, const float* __restrict__ Whh,
                       const float* __restrict__ W1mu, const float* __restrict__ W2mu,
                       const float* __restrict__ W1o, const float* __restrict__ W2o) {
  __shared__ float S[10240];               // 40 KB, aliased per role
  const int bx = blockIdx.x, t = threadIdx.x;
  if (bx < 512) {
    // ---------------- kA role: fused LayerNorm + k = xn @ Wk^T ----------------
    float* xs = S;                         // 64*128
    float* wt = S + 8192;                  // 16*128
    const int r0blk = bx*64;
    for (int idx=t; idx<64*DD; idx+=256) xs[idx] = inp[(long)r0blk*DD + idx];
    __syncthreads();
    { // LayerNorm: warp w -> rows w*8..w*8+7
      int w = t>>5, lane = t&31;
      for (int r=w*8; r<w*8+8; ++r) {
        float x0=xs[r*DD+lane],    x1=xs[r*DD+lane+32];
        float x2=xs[r*DD+lane+64], x3=xs[r*DD+lane+96];
        float s = x0+x1+x2+x3;
        #pragma unroll
        for (int o=16;o;o>>=1) s += __shfl_xor_sync(0xffffffffu,s,o);
        float m = s*(1.f/128.f);
        float d0=x0-m,d1=x1-m,d2=x2-m,d3=x3-m;
        float s2 = d0*d0+d1*d1+d2*d2+d3*d3;
        #pragma unroll
        for (int o=16;o;o>>=1) s2 += __shfl_xor_sync(0xffffffffu,s2,o);
        float rs = rsqrtf(s2*(1.f/128.f)+1e-5f);
        xs[r*DD+lane]    = d0*rs*lng[lane]    + lnb[lane];
        xs[r*DD+lane+32] = d1*rs*lng[lane+32] + lnb[lane+32];
        xs[r*DD+lane+64] = d2*rs*lng[lane+64] + lnb[lane+64];
        xs[r*DD+lane+96] = d3*rs*lng[lane+96] + lnb[lane+96];
      }
    }
    const int cg = t&31, rg = t>>5;
    const int c0 = cg*4, r0 = rg*8;
    float4 acc[8];
    #pragma unroll
    for (int r=0;r<8;++r) acc[r] = make_float4(0.f,0.f,0.f,0.f);
    for (int kt=0; kt<8; ++kt) {
      __syncthreads();
      // stage raw Wk: wt[kk*128+c] = Wk[c*128 + kt*16+kk]
      for (int i=t; i<16*DD; i+=256) {
        int kk = i>>7, c = i&127;
        wt[i] = Wk[c*DD + kt*16 + kk];
      }
      __syncthreads();
      #pragma unroll 4
      for (int kk=0;kk<16;++kk) {
        float4 wv = *(const float4*)&wt[kk*DD+c0];
        int kg = kt*16 + kk;
        #pragma unroll
        for (int r=0;r<8;++r) {
          float xv = xs[(r0+r)*DD+kg];
          acc[r].x = fmaf(xv,wv.x,acc[r].x);
          acc[r].y = fmaf(xv,wv.y,acc[r].y);
          acc[r].z = fmaf(xv,wv.z,acc[r].z);
          acc[r].w = fmaf(xv,wv.w,acc[r].w);
        }
      }
    }
    #pragma unroll
    for (int r=0;r<8;++r)
      *(float4*)&g_k[(long)(r0blk + r0 + r)*DD + c0] = acc[r];
  } else if (bx < 576) {
    // ---------------- transpose role ----------------
    int tid = (bx-512)*256 + t;
    int stride = 64*256;
    for (int i=tid;i<DD*DD;i+=stride){int d=i>>7,c=i&127;  g_WqT[c*DD+d]=Wq[i];}
    for (int i=tid;i<3*DD*DD;i+=stride){int j=i>>7,c=i&127; g_WihT[c*384+j]=Wih[i]; g_WhhT[c*384+j]=Whh[i];}
    for (int i=tid;i<HH*DD;i+=stride){int j=i>>7,c=i&127;  g_W1muT[c*HH+j]=W1mu[i];}
    for (int i=tid;i<DD*HH;i+=stride){int d=i>>7,j=i&127;  g_W2muT[j*DD+d]=W2mu[i];}
    for (int i=tid;i<2*HH*2*DD;i+=stride){int j=i>>8,c=i&255; g_W1oT[c*256+j]=W1o[i];}
    for (int i=tid;i<DD*2*HH;i+=stride){int d=i>>8,c=i&255; g_W2oT[c*DD+d]=W2o[i];}
  } else {
    // ---------------- init role: slot init + pi + first Q-phase (raw Wq) ------
    float* sv  = S;
    float* sn  = S + 256;
    float* tmp = S + 512;
    float* red = S + 640;
    int r = bx - 576;
    sv[t] = smu[t] + expf(slsig[t])*noise[r*256+t];
    if (t==0) g_pi[r] = 1.f/(float)NSL;
    __syncthreads();
    float x = sv[t];
    float m = blkSum8(x, red, t) * (1.f/256.f);
    float dv = x - m;
    float var = blkSum8(dv*dv, red, t) * (1.f/256.f);
    float rs = rsqrtf(var + 1e-5f);
    sn[t] = dv*rs*lsg[t] + lsb[t];
    __syncthreads();
    int idx = t & 127;
    const float* s = (t < 128) ? &sn[0] : &sn[128];
    float acc = 0.f;
    #pragma unroll 16
    for (int c=0;c<128;++c) acc = fmaf(s[c], Wq[idx*DD+c], acc);
    if (t >= 128) {
      float inv = expf(-2.f*acc);
      g_wa[r*DD+idx] = inv;
      tmp[idx] = inv;
    }
    __syncthreads();
    float cpart = 0.f;
    if (t < 128) {
      float inv = tmp[t];
      g_wb[r*DD+t] = -2.f*inv*acc;
      g_mus[r*DD+t] = sn[t];
      g_accV[r*DD+t] = 0.f;
      g_accV2[r*DD+t] = 0.f;
      cpart = inv*acc*acc;
    }
    float C = blkSum8(cpart, red, t);
    if (t==0) { g_wc[r] = C; g_gsum[r] = 0.f; }
  }
}

// ---------------- Q-phase: LN(slots) + Wq -> wa/wb/wc, 256 threads, 1 row ------
__device__ __forceinline__ void qphase(int r, const float* sv, float* sn,
                                       float* tmp, float* red,
                                       const float* __restrict__ lsg,
                                       const float* __restrict__ lsb, int t) {
  float x = sv[t];
  float m = blkSum8(x, red, t) * (1.f/256.f);
  float dv = x - m;
  float var = blkSum8(dv*dv, red, t) * (1.f/256.f);
  float rs = rsqrtf(var + 1e-5f);
  sn[t] = dv*rs*lsg[t] + lsb[t];
  __syncthreads();
  int idx = t & 127;
  const float* s = (t < 128) ? &sn[0] : &sn[128];
  float acc = 0.f;
  #pragma unroll 16
  for (int c=0;c<128;++c) acc = fmaf(s[c], g_WqT[c*DD+idx], acc);
  if (t >= 128) {
    float inv = expf(-2.f*acc);
    g_wa[r*DD+idx] = inv;
    tmp[idx] = inv;
  }
  __syncthreads();
  float cpart = 0.f;
  if (t < 128) {
    float inv = tmp[t];
    g_wb[r*DD+t] = -2.f*inv*acc;
    g_mus[r*DD+t] = sn[t];
    g_accV[r*DD+t] = 0.f;
    g_accV2[r*DD+t] = 0.f;
    cpart = inv*acc*acc;
  }
  float C = blkSum8(cpart, red, t);
  if (t==0) { g_wc[r] = C; g_gsum[r] = 0.f; }
}

// ---------------- kP: fused dots/gamma/moment pass -----------------------------
// grid (16 b, 64 chunks of 32 n), 128 threads; ~26.5 KB smem, 8 blocks/SM
__global__ void __launch_bounds__(128, 8) kP() {
  __shared__ float4 ks4[CH2*KSTR];         // 16896 B
  __shared__ float4 wa4[8*KSTR];           // 4224 B
  __shared__ float4 wb4[8*KSTR];           // 4224 B
  __shared__ float pd[8*CH2];              // 1024 B  [s][n] complete dots
  __shared__ float gm[CH2*8];              // 1024 B  [n][s]
  __shared__ float sC[8], sPi[8];
  int b = blockIdx.x, chunk = blockIdx.y;
  int tid = threadIdx.x, lane = tid&31, w = tid>>5;
  { // stage wa/wb: 8 slots x 32 float4 each
    for (int i=tid; i<256; i+=128) {
      int s = i>>5, d4 = i&31;
      wa4[s*KSTR+d4] = ((const float4*)&g_wa[(b*8+s)*DD])[d4];
      wb4[s*KSTR+d4] = ((const float4*)&g_wb[(b*8+s)*DD])[d4];
    }
  }
  if (tid<8) { sC[tid] = g_wc[b*8+tid]; sPi[tid] = g_pi[b*8+tid]; }
  { // stage k tile: 32 rows x 32 float4, coalesced
    const float4* src = (const float4*)&g_k[(long)b*NN*DD + (long)chunk*CH2*DD];
    #pragma unroll
    for (int rep=0; rep<8; ++rep) {
      int i = rep*128 + tid;
      ks4[(i>>5)*KSTR + (i&31)] = src[i];
    }
  }
  __syncthreads();
  // phase 1: thread = (n = lane, sg = warp); 2 complete dots over 128 d
  {
    int n = lane, sg = w;
    int s0 = sg*2, s1 = sg*2+1;
    const float4* kr  = &ks4[n*KSTR];
    const float4* wa0 = &wa4[s0*KSTR];
    const float4* wb0 = &wb4[s0*KSTR];
    const float4* wa1 = &wa4[s1*KSTR];
    const float4* wb1 = &wb4[s1*KSTR];
    float d0 = 0.f, d1 = 0.f;
    #pragma unroll 8
    for (int i=0;i<32;++i) {
      float4 k4 = kr[i];
      float4 a4 = wa0[i], b4 = wb0[i];
      float p = fmaf(a4.x,k4.x,b4.x)*k4.x;
      p = fmaf(fmaf(a4.y,k4.y,b4.y), k4.y, p);
      p = fmaf(fmaf(a4.z,k4.z,b4.z), k4.z, p);
      p = fmaf(fmaf(a4.w,k4.w,b4.w), k4.w, p);
      d0 += p;
      float4 a5 = wa1[i], b5 = wb1[i];
      float q = fmaf(a5.x,k4.x,b5.x)*k4.x;
      q = fmaf(fmaf(a5.y,k4.y,b5.y), k4.y, q);
      q = fmaf(fmaf(a5.z,k4.z,b5.z), k4.z, q);
      q = fmaf(fmaf(a5.w,k4.w,b5.w), k4.w, q);
      d1 += q;
    }
    pd[s0*CH2+n] = d0;
    pd[s1*CH2+n] = d1;
  }
  __syncthreads();
  // phase 1b: threads 0..31 (n) do exp + softmax over 8 slots
  if (tid < CH2) {
    int n = tid;
    float e[8], ssum = 0.f;
    #pragma unroll
    for (int s=0;s<8;++s) {
      float dot = pd[s*CH2+n] + sC[s];
      e[s] = (expf(-dot) + EPSV) * sPi[s];
      ssum += e[s];
    }
    float inv = 1.f/ssum;
    #pragma unroll
    for (int s=0;s<8;++s) gm[n*8+s] = e[s]*inv;
  }
  __syncthreads();
  // phase 2: warp = slot-pair; lane = d4; full 32 n
  {
    int s0 = w*2, s1 = w*2+1;
    float4 aV0 = make_float4(0,0,0,0), a20 = make_float4(0,0,0,0);
    float4 aV1 = make_float4(0,0,0,0), a21 = make_float4(0,0,0,0);
    float gs0 = 0.f, gs1 = 0.f;
    #pragma unroll 4
    for (int n=0; n<CH2; ++n) {
      float4 k4 = ks4[n*KSTR+lane];
      float2 g2 = *(const float2*)&gm[n*8 + s0];
      float g0 = g2.x, g1 = g2.y;
      gs0 += g0; gs1 += g1;
      float sx = k4.x*k4.x, sy = k4.y*k4.y, sz = k4.z*k4.z, sw = k4.w*k4.w;
      aV0.x = fmaf(g0,k4.x,aV0.x); aV0.y = fmaf(g0,k4.y,aV0.y);
      aV0.z = fmaf(g0,k4.z,aV0.z); aV0.w = fmaf(g0,k4.w,aV0.w);
      a20.x = fmaf(g0,sx,a20.x); a20.y = fmaf(g0,sy,a20.y);
      a20.z = fmaf(g0,sz,a20.z); a20.w = fmaf(g0,sw,a20.w);
      aV1.x = fmaf(g1,k4.x,aV1.x); aV1.y = fmaf(g1,k4.y,aV1.y);
      aV1.z = fmaf(g1,k4.z,aV1.z); aV1.w = fmaf(g1,k4.w,aV1.w);
      a21.x = fmaf(g1,sx,a21.x); a21.y = fmaf(g1,sy,a21.y);
      a21.z = fmaf(g1,sz,a21.z); a21.w = fmaf(g1,sw,a21.w);
    }
    float* pV0 = &g_accV [(b*8+s0)*DD + lane*4];
    float* p20 = &g_accV2[(b*8+s0)*DD + lane*4];
    float* pV1 = &g_accV [(b*8+s1)*DD + lane*4];
    float* p21 = &g_accV2[(b*8+s1)*DD + lane*4];
    atomicAdd(pV0+0,aV0.x); atomicAdd(pV0+1,aV0.y);
    atomicAdd(pV0+2,aV0.z); atomicAdd(pV0+3,aV0.w);
    atomicAdd(p20+0,a20.x); atomicAdd(p20+1,a20.y);
    atomicAdd(p20+2,a20.z); atomicAdd(p20+3,a20.w);
    atomicAdd(pV1+0,aV1.x); atomicAdd(pV1+1,aV1.y);
    atomicAdd(pV1+2,aV1.z); atomicAdd(pV1+3,aV1.w);
    atomicAdd(p21+0,a21.x); atomicAdd(p21+1,a21.y);
    atomicAdd(p21+2,a21.z); atomicAdd(p21+3,a21.w);
    if (lane==0) { atomicAdd(&g_gsum[b*8+s0], gs0); atomicAdd(&g_gsum[b*8+s1], gs1); }
  }
}

// ---------------- kUQ: GRU + LN + MLP + logsigma, then Q-phase (or final MLP) ----
// 128 blocks (slot rows), 256 threads; GRU weights reg-double-buffered via smem
__global__ void kUQ(const float* __restrict__ bih, const float* __restrict__ bhh,
                    const float* __restrict__ b1, const float* __restrict__ b2,
                    const float* __restrict__ lmg, const float* __restrict__ lmb,
                    const float* __restrict__ lsg, const float* __restrict__ lsb,
                    const float* __restrict__ b1o, const float* __restrict__ b2o,
                    float* __restrict__ outp, int last) {
  __shared__ float swih[8*384];            // 12 KB weight stage
  __shared__ float swhh[8*384];            // 12 KB
  __shared__ float s1s[128], s2s[128], mus[128];
  __shared__ float ps[6*256];
  __shared__ float hs[128];
  __shared__ float m1[128];
  __shared__ float sv[256];
  __shared__ float sn[256];
  __shared__ float tmp[128];
  __shared__ float red[8];
  int r = blockIdx.x, t = threadIdx.x, tt = t & 127, th = t >> 7;
  float gsum = g_gsum[r];
  if (t < 128) {
    float inv = 1.f/gsum;
    s1s[t] = g_accV[r*DD+t]*inv;
    s2s[t] = g_accV2[r*DD+t]*inv;
    mus[t] = g_mus[r*DD+t];
  }
  __syncthreads();
  // GRU gates: 16 chunks of 8 c-rows, register double-buffered staging
  {
    const float4* giT = (const float4*)g_WihT;
    const float4* ghT = (const float4*)g_WhhT;
    float4 ri[3], rh[3];
    #pragma unroll
    for (int rep=0;rep<3;++rep) { ri[rep]=giT[rep*256+t]; rh[rep]=ghT[rep*256+t]; }
    float gir=0,giz=0,gin=0,ghr=0,ghz=0,ghn=0;
    for (int ch=0; ch<16; ++ch) {
      __syncthreads();
      #pragma unroll
      for (int rep=0;rep<3;++rep) {
        ((float4*)swih)[rep*256+t]=ri[rep];
        ((float4*)swhh)[rep*256+t]=rh[rep];
      }
      __syncthreads();
      if (ch<15) {
        #pragma unroll
        for (int rep=0;rep<3;++rep) {
          ri[rep]=giT[(ch+1)*768+rep*256+t];
          rh[rep]=ghT[(ch+1)*768+rep*256+t];
        }
      }
      int cl0 = th*4;
      #pragma unroll
      for (int ci=0; ci<4; ++ci) {
        int cl = cl0 + ci, c = ch*8 + cl;
        float xv = s1s[c], hv = mus[c];
        const float* wi = &swih[cl*384];
        const float* wh = &swhh[cl*384];
        gir = fmaf(xv, wi[tt],     gir);  ghr = fmaf(hv, wh[tt],     ghr);
        giz = fmaf(xv, wi[128+tt], giz);  ghz = fmaf(hv, wh[128+tt], ghz);
        gin = fmaf(xv, wi[256+tt], gin);  ghn = fmaf(hv, wh[256+tt], ghn);
      }
    }
    ps[t]=gir; ps[256+t]=giz; ps[512+t]=gin;
    ps[768+t]=ghr; ps[1024+t]=ghz; ps[1280+t]=ghn;
  }
  __syncthreads();
  float upd1 = 0.f;
  if (t < 128) {
    float Gir = ps[t]+ps[t+128]       + bih[t];
    float Giz = ps[256+t]+ps[384+t]   + bih[128+t];
    float Gin = ps[512+t]+ps[640+t]   + bih[256+t];
    float Ghr = ps[768+t]+ps[896+t]   + bhh[t];
    float Ghz = ps[1024+t]+ps[1152+t] + bhh[128+t];
    float Ghn = ps[1280+t]+ps[1408+t] + bhh[256+t];
    float rg = 1.f/(1.f+expf(-(Gir+Ghr)));
    float zg = 1.f/(1.f+expf(-(Giz+Ghz)));
    float ng = tanhf(Gin + rg*Ghn);
    upd1 = (1.f-zg)*ng + zg*mus[t];
  }
  __syncthreads();
  // LN(upd1) over 128 (inactive threads contribute 0)
  {
    float v = (t<128) ? upd1 : 0.f;
    float m = blkSum8(v, red, t) * (1.f/128.f);
    float dv = (t<128) ? (upd1 - m) : 0.f;
    float var = blkSum8(dv*dv, red, t) * (1.f/128.f);
    float rs = rsqrtf(var + 1e-5f);
    if (t<128) hs[t] = dv*rs*lmg[t] + lmb[t];
  }
  __syncthreads();
  // MLP1: split c over halves
  {
    float a = 0.f;
    int c0 = th*64;
    #pragma unroll 16
    for (int c=c0; c<c0+64; ++c) a = fmaf(hs[c], g_W1muT[c*HH+tt], a);
    ps[t] = a;
  }
  __syncthreads();
  if (t < 128) m1[t] = fmaxf(ps[t]+ps[t+128]+b1[t], 0.f);
  __syncthreads();
  // MLP2: split j over halves
  {
    float a = 0.f;
    int j0 = th*64;
    #pragma unroll 16
    for (int j=j0; j<j0+64; ++j) a = fmaf(m1[j], g_W2muT[j*DD+tt], a);
    ps[t] = a;
  }
  __syncthreads();
  if (t < 128) {
    float out = upd1 + b2[t] + ps[t] + ps[t+128];
    float ls = 0.5f*logf(s2s[t] - 2.f*out*s1s[t] + out*out + EPSV);
    sv[t] = out;
    sv[128+t] = ls;
    if (t==0) g_pi[r] = gsum;
  }
  __syncthreads();
  if (!last) {
    qphase(r, sv, sn, tmp, red, lsg, lsb, t);
  } else {
    // final output MLP: h = relu(sv @ W1o^T + b1o), out = h @ W2o^T + b2o
    float a = b1o[t];
    #pragma unroll 16
    for (int c=0;c<256;++c) a = fmaf(sv[c], g_W1oT[c*256+t], a);
    sn[t] = fmaxf(a, 0.f);
    __syncthreads();
    if (t < 128) {
      float o = b2o[t];
      #pragma unroll 16
      for (int c=0;c<256;++c) o = fmaf(sn[c], g_W2oT[c*DD+t], o);
      outp[r*DD+t] = o;
    }
  }
}

extern "C" void kernel_launch(void* const* d_in, const int* in_sizes, int n_in,
                              void* d_out, int out_size) {
  const float* inputs  = (const float*)d_in[0];
  const float* noise   = (const float*)d_in[1];
  const float* smu     = (const float*)d_in[2];
  const float* slsig   = (const float*)d_in[3];
  const float* Wq      = (const float*)d_in[4];
  const float* Wk      = (const float*)d_in[5];
  const float* Wih     = (const float*)d_in[6];
  const float* Whh     = (const float*)d_in[7];
  const float* bih     = (const float*)d_in[8];
  const float* bhh     = (const float*)d_in[9];
  const float* W1mu    = (const float*)d_in[10];
  const float* b1mu    = (const float*)d_in[11];
  const float* W2mu    = (const float*)d_in[12];
  const float* b2mu    = (const float*)d_in[13];
  const float* ln_in_g = (const float*)d_in[14];
  const float* ln_in_b = (const float*)d_in[15];
  const float* lsg     = (const float*)d_in[16];
  const float* lsb     = (const float*)d_in[17];
  const float* lmg     = (const float*)d_in[18];
  const float* lmb     = (const float*)d_in[19];
  const float* W1o     = (const float*)d_in[20];
  const float* b1o     = (const float*)d_in[21];
  const float* W2o     = (const float*)d_in[22];
  const float* b2o     = (const float*)d_in[23];
  float* out = (float*)d_out;

  kFused<<<704, 256>>>(inputs, ln_in_g, ln_in_b, noise, smu, slsig, lsg, lsb,
                       Wq, Wk, Wih, Whh, W1mu, W2mu, W1o, W2o);
  for (int it=0; it<4; ++it) {
    kP<<<dim3(BB, NN/CH2), 128>>>();
    kUQ<<<RWS, 256>>>(bih, bhh, b1mu, b2mu, lmg, lmb, lsg, lsb,
                      b1o, b2o, out, it==3 ? 1 : 0);
  }
}

// round 15
// speedup vs baseline: 1.0107x; 1.0107x over previous
#include <cuda_runtime.h>
#include <math.h>

#define BB   16
#define NN   2048
#define DD   128
#define NSL  8
#define HH   128
#define RWS  (BB*NSL)            // 128 slot rows
#define EPSV 1e-8f
#define CH   64                  // n-rows per kP chunk
#define KSTR 33                  // float4 stride for ks rows

// ---------------- scratch (__device__ globals: allocation-free) ----------------
__device__ float g_k[BB*NN*DD];          // 16 MB, k == v
__device__ float g_mus[RWS*DD];          // mu_s (GRU hidden)
__device__ float g_wa[RWS*DD];           // inv_var
__device__ float g_wb[RWS*DD];           // -2*inv*qmu
__device__ float g_wc[RWS];              // sum inv*qmu^2
__device__ float g_pi[RWS];
__device__ float g_gsum[RWS];
__device__ float g_accV[RWS*DD];
__device__ float g_accV2[RWS*DD];

// transposed weights
__device__ float g_WkT[DD*DD];           // [kk][c]
__device__ float g_WqT[DD*DD];           // [c][d]
__device__ float g_WihT[DD*3*DD];        // [c][j]
__device__ float g_WhhT[DD*3*DD];
__device__ float g_W1muT[DD*HH];         // [c][j]
__device__ float g_W2muT[HH*DD];         // [j][d]
__device__ float g_W1oT[2*DD*2*HH];      // [c][j]
__device__ float g_W2oT[2*HH*DD];        // [c][d]

// ---------------- 8-warp block reduce ----------------
__device__ __forceinline__ float blkSum8(float v, float* red, int tid) {
  int lane = tid&31, w = tid>>5;
  #pragma unroll
  for (int o=16;o;o>>=1) v += __shfl_xor_sync(0xffffffffu,v,o);
  if (lane==0) red[w] = v;
  __syncthreads();
  float tot = red[0]+red[1]+red[2]+red[3]+red[4]+red[5]+red[6]+red[7];
  __syncthreads();
  return tot;
}

// ---------------- kInitT: transposes (blocks 0-63) + slot init/first Q-phase
//                  with raw Wq (blocks 64-191); 256 threads --------------------
__global__ void kInitT(const float* __restrict__ noise, const float* __restrict__ smu,
                       const float* __restrict__ slsig,
                       const float* __restrict__ lsg, const float* __restrict__ lsb,
                       const float* __restrict__ Wq, const float* __restrict__ Wk,
                       const float* __restrict__ Wih, const float* __restrict__ Whh,
                       const float* __restrict__ W1mu, const float* __restrict__ W2mu,
                       const float* __restrict__ W1o, const float* __restrict__ W2o) {
  __shared__ float sv[256];
  __shared__ float sn[256];
  __shared__ float tmp[128];
  __shared__ float red[8];
  int bx = blockIdx.x, t = threadIdx.x;
  if (bx < 64) {
    // -------- transpose role --------
    int tid = bx*256 + t;
    int stride = 64*256;
    for (int i=tid;i<DD*DD;i+=stride){int c=i>>7,kk=i&127; g_WkT[kk*DD+c]=Wk[i];}
    for (int i=tid;i<DD*DD;i+=stride){int d=i>>7,c=i&127;  g_WqT[c*DD+d]=Wq[i];}
    for (int i=tid;i<3*DD*DD;i+=stride){int j=i>>7,c=i&127; g_WihT[c*384+j]=Wih[i]; g_WhhT[c*384+j]=Whh[i];}
    for (int i=tid;i<HH*DD;i+=stride){int j=i>>7,c=i&127;  g_W1muT[c*HH+j]=W1mu[i];}
    for (int i=tid;i<DD*HH;i+=stride){int d=i>>7,j=i&127;  g_W2muT[j*DD+d]=W2mu[i];}
    for (int i=tid;i<2*HH*2*DD;i+=stride){int j=i>>8,c=i&255; g_W1oT[c*256+j]=W1o[i];}
    for (int i=tid;i<DD*2*HH;i+=stride){int d=i>>8,c=i&255; g_W2oT[c*DD+d]=W2o[i];}
  } else {
    // -------- init role: slot init + pi + first Q-phase (raw Wq) --------
    int r = bx - 64;
    sv[t] = smu[t] + expf(slsig[t])*noise[r*256+t];
    if (t==0) g_pi[r] = 1.f/(float)NSL;
    __syncthreads();
    float x = sv[t];
    float m = blkSum8(x, red, t) * (1.f/256.f);
    float dv = x - m;
    float var = blkSum8(dv*dv, red, t) * (1.f/256.f);
    float rs = rsqrtf(var + 1e-5f);
    sn[t] = dv*rs*lsg[t] + lsb[t];
    __syncthreads();
    int idx = t & 127;
    const float* s = (t < 128) ? &sn[0] : &sn[128];
    float acc = 0.f;
    #pragma unroll 16
    for (int c=0;c<128;++c) acc = fmaf(s[c], Wq[idx*DD+c], acc);
    if (t >= 128) {
      float inv = expf(-2.f*acc);
      g_wa[r*DD+idx] = inv;
      tmp[idx] = inv;
    }
    __syncthreads();
    float cpart = 0.f;
    if (t < 128) {
      float inv = tmp[t];
      g_wb[r*DD+t] = -2.f*inv*acc;
      g_mus[r*DD+t] = sn[t];
      g_accV[r*DD+t] = 0.f;
      g_accV2[r*DD+t] = 0.f;
      cpart = inv*acc*acc;
    }
    float C = blkSum8(cpart, red, t);
    if (t==0) { g_wc[r] = C; g_gsum[r] = 0.f; }
  }
}

// ---------------- kA: fused LayerNorm + k = xn @ Wk^T ----------------
__global__ void kA(const float* __restrict__ inp,
                   const float* __restrict__ lng, const float* __restrict__ lnb) {
  __shared__ float xs[64*DD];
  __shared__ float wt[16*DD];
  const int tid = threadIdx.x;
  const int r0blk = blockIdx.x*64;
  for (int idx=tid; idx<64*DD; idx+=256) xs[idx] = inp[(long)r0blk*DD + idx];
  __syncthreads();
  { // LayerNorm: warp w -> rows w*8..w*8+7
    int w = tid>>5, lane = tid&31;
    for (int r=w*8; r<w*8+8; ++r) {
      float x0=xs[r*DD+lane],    x1=xs[r*DD+lane+32];
      float x2=xs[r*DD+lane+64], x3=xs[r*DD+lane+96];
      float s = x0+x1+x2+x3;
      #pragma unroll
      for (int o=16;o;o>>=1) s += __shfl_xor_sync(0xffffffffu,s,o);
      float m = s*(1.f/128.f);
      float d0=x0-m,d1=x1-m,d2=x2-m,d3=x3-m;
      float s2 = d0*d0+d1*d1+d2*d2+d3*d3;
      #pragma unroll
      for (int o=16;o;o>>=1) s2 += __shfl_xor_sync(0xffffffffu,s2,o);
      float rs = rsqrtf(s2*(1.f/128.f)+1e-5f);
      xs[r*DD+lane]    = d0*rs*lng[lane]    + lnb[lane];
      xs[r*DD+lane+32] = d1*rs*lng[lane+32] + lnb[lane+32];
      xs[r*DD+lane+64] = d2*rs*lng[lane+64] + lnb[lane+64];
      xs[r*DD+lane+96] = d3*rs*lng[lane+96] + lnb[lane+96];
    }
  }
  const int cg = tid&31, rg = tid>>5;
  const int c0 = cg*4, r0 = rg*8;
  float4 acc[8];
  #pragma unroll
  for (int r=0;r<8;++r) acc[r] = make_float4(0.f,0.f,0.f,0.f);
  for (int kt=0; kt<8; ++kt) {
    __syncthreads();
    for (int i=tid; i<16*DD; i+=256) wt[i] = g_WkT[kt*16*DD + i];
    __syncthreads();
    #pragma unroll 4
    for (int kk=0;kk<16;++kk) {
      float4 wv = *(const float4*)&wt[kk*DD+c0];
      int kg = kt*16 + kk;
      #pragma unroll
      for (int r=0;r<8;++r) {
        float xv = xs[(r0+r)*DD+kg];
        acc[r].x = fmaf(xv,wv.x,acc[r].x);
        acc[r].y = fmaf(xv,wv.y,acc[r].y);
        acc[r].z = fmaf(xv,wv.z,acc[r].z);
        acc[r].w = fmaf(xv,wv.w,acc[r].w);
      }
    }
  }
  #pragma unroll
  for (int r=0;r<8;++r)
    *(float4*)&g_k[(long)(r0blk + r0 + r)*DD + c0] = acc[r];
}

// ---------------- Q-phase: LN(slots) + Wq -> wa/wb/wc, 256 threads, 1 row ------
__device__ __forceinline__ void qphase(int r, const float* sv, float* sn,
                                       float* tmp, float* red,
                                       const float* __restrict__ lsg,
                                       const float* __restrict__ lsb, int t) {
  float x = sv[t];
  float m = blkSum8(x, red, t) * (1.f/256.f);
  float dv = x - m;
  float var = blkSum8(dv*dv, red, t) * (1.f/256.f);
  float rs = rsqrtf(var + 1e-5f);
  sn[t] = dv*rs*lsg[t] + lsb[t];
  __syncthreads();
  int idx = t & 127;
  const float* s = (t < 128) ? &sn[0] : &sn[128];
  float acc = 0.f;
  #pragma unroll 16
  for (int c=0;c<128;++c) acc = fmaf(s[c], g_WqT[c*DD+idx], acc);
  if (t >= 128) {
    float inv = expf(-2.f*acc);
    g_wa[r*DD+idx] = inv;
    tmp[idx] = inv;
  }
  __syncthreads();
  float cpart = 0.f;
  if (t < 128) {
    float inv = tmp[t];
    g_wb[r*DD+t] = -2.f*inv*acc;
    g_mus[r*DD+t] = sn[t];
    g_accV[r*DD+t] = 0.f;
    g_accV2[r*DD+t] = 0.f;
    cpart = inv*acc*acc;
  }
  float C = blkSum8(cpart, red, t);
  if (t==0) { g_wc[r] = C; g_gsum[r] = 0.f; }
}

// ---------------- kP: fused dots/gamma/moment pass -----------------------------
// grid (16 b, 32 chunks of 64 n), 256 threads; 46.3 KB static smem
__global__ void __launch_bounds__(256, 4) kP() {
  __shared__ float4 ks4[CH*KSTR];          // 33792 B
  __shared__ float4 wa4[8*KSTR];           // 4224 B
  __shared__ float4 wb4[8*KSTR];           // 4224 B
  __shared__ float pd[8*64];               // 2048 B  [s][n] complete dots
  __shared__ float gm[CH*8];               // 2048 B  [n][s]
  __shared__ float sC[8], sPi[8];
  int b = blockIdx.x, chunk = blockIdx.y;
  int tid = threadIdx.x, lane = tid&31, w = tid>>5;
  { // stage wa/wb: 8 slots x 32 float4
    int s = tid>>5, i = tid&31;
    wa4[s*KSTR+i] = ((const float4*)&g_wa[(b*8+s)*DD])[i];
    wb4[s*KSTR+i] = ((const float4*)&g_wb[(b*8+s)*DD])[i];
  }
  if (tid<8) { sC[tid] = g_wc[b*8+tid]; sPi[tid] = g_pi[b*8+tid]; }
  { // stage k tile: 64 rows x 32 float4, coalesced
    const float4* src = (const float4*)&g_k[(long)b*NN*DD + (long)chunk*CH*DD];
    #pragma unroll
    for (int rep=0; rep<8; ++rep) {
      int i = rep*256 + tid;
      ks4[(i>>5)*KSTR + (i&31)] = src[i];
    }
  }
  __syncthreads();
  // phase 1: thread = (n = tid&63, sg = tid>>6); 2 complete dots over 128 d
  {
    int n = tid&63, sg = tid>>6;
    int s0 = sg*2, s1 = sg*2+1;
    const float4* kr  = &ks4[n*KSTR];
    const float4* wa0 = &wa4[s0*KSTR];
    const float4* wb0 = &wb4[s0*KSTR];
    const float4* wa1 = &wa4[s1*KSTR];
    const float4* wb1 = &wb4[s1*KSTR];
    float d0 = 0.f, d1 = 0.f;
    #pragma unroll 8
    for (int i=0;i<32;++i) {
      float4 k4 = kr[i];
      float4 a4 = wa0[i], b4 = wb0[i];
      float p = fmaf(a4.x,k4.x,b4.x)*k4.x;
      p = fmaf(fmaf(a4.y,k4.y,b4.y), k4.y, p);
      p = fmaf(fmaf(a4.z,k4.z,b4.z), k4.z, p);
      p = fmaf(fmaf(a4.w,k4.w,b4.w), k4.w, p);
      d0 += p;
      float4 a5 = wa1[i], b5 = wb1[i];
      float q = fmaf(a5.x,k4.x,b5.x)*k4.x;
      q = fmaf(fmaf(a5.y,k4.y,b5.y), k4.y, q);
      q = fmaf(fmaf(a5.z,k4.z,b5.z), k4.z, q);
      q = fmaf(fmaf(a5.w,k4.w,b5.w), k4.w, q);
      d1 += q;
    }
    pd[s0*64+n] = d0;
    pd[s1*64+n] = d1;
  }
  __syncthreads();
  // phase 1b: threads 0..63 (n) do exp + softmax over 8 slots
  if (tid < 64) {
    int n = tid;
    float e[8], ssum = 0.f;
    #pragma unroll
    for (int s=0;s<8;++s) {
      float dot = pd[s*64+n] + sC[s];
      e[s] = (expf(-dot) + EPSV) * sPi[s];
      ssum += e[s];
    }
    float inv = 1.f/ssum;
    #pragma unroll
    for (int s=0;s<8;++s) gm[n*8+s] = e[s]*inv;
  }
  __syncthreads();
  // phase 2: warp = (slot-pair, n-half); lane = d4
  {
    int sp = w & 3, nh = w >> 2;
    int s0 = sp*2, s1 = sp*2+1;
    float4 aV0 = make_float4(0,0,0,0), a20 = make_float4(0,0,0,0);
    float4 aV1 = make_float4(0,0,0,0), a21 = make_float4(0,0,0,0);
    float gs0 = 0.f, gs1 = 0.f;
    #pragma unroll 4
    for (int ni=0; ni<32; ++ni) {
      int n = nh*32 + ni;
      float4 k4 = ks4[n*KSTR+lane];
      float2 g2 = *(const float2*)&gm[n*8 + s0];
      float g0 = g2.x, g1 = g2.y;
      gs0 += g0; gs1 += g1;
      float sx = k4.x*k4.x, sy = k4.y*k4.y, sz = k4.z*k4.z, sw = k4.w*k4.w;
      aV0.x = fmaf(g0,k4.x,aV0.x); aV0.y = fmaf(g0,k4.y,aV0.y);
      aV0.z = fmaf(g0,k4.z,aV0.z); aV0.w = fmaf(g0,k4.w,aV0.w);
      a20.x = fmaf(g0,sx,a20.x); a20.y = fmaf(g0,sy,a20.y);
      a20.z = fmaf(g0,sz,a20.z); a20.w = fmaf(g0,sw,a20.w);
      aV1.x = fmaf(g1,k4.x,aV1.x); aV1.y = fmaf(g1,k4.y,aV1.y);
      aV1.z = fmaf(g1,k4.z,aV1.z); aV1.w = fmaf(g1,k4.w,aV1.w);
      a21.x = fmaf(g1,sx,a21.x); a21.y = fmaf(g1,sy,a21.y);
      a21.z = fmaf(g1,sw*0.f+sz,a21.z); a21.w = fmaf(g1,sw,a21.w);
    }
    float* pV0 = &g_accV [(b*8+s0)*DD + lane*4];
    float* p20 = &g_accV2[(b*8+s0)*DD + lane*4];
    float* pV1 = &g_accV [(b*8+s1)*DD + lane*4];
    float* p21 = &g_accV2[(b*8+s1)*DD + lane*4];
    atomicAdd(pV0+0,aV0.x); atomicAdd(pV0+1,aV0.y);
    atomicAdd(pV0+2,aV0.z); atomicAdd(pV0+3,aV0.w);
    atomicAdd(p20+0,a20.x); atomicAdd(p20+1,a20.y);
    atomicAdd(p20+2,a20.z); atomicAdd(p20+3,a20.w);
    atomicAdd(pV1+0,aV1.x); atomicAdd(pV1+1,aV1.y);
    atomicAdd(pV1+2,aV1.z); atomicAdd(pV1+3,aV1.w);
    atomicAdd(p21+0,a21.x); atomicAdd(p21+1,a21.y);
    atomicAdd(p21+2,a21.z); atomicAdd(p21+3,a21.w);
    if (lane==0) { atomicAdd(&g_gsum[b*8+s0], gs0); atomicAdd(&g_gsum[b*8+s1], gs1); }
  }
}

// ---------------- kUQ: GRU + LN + MLP + logsigma, then Q-phase (or final MLP) ----
// 128 blocks (slot rows), 256 threads; GRU weights reg-double-buffered via smem
__global__ void kUQ(const float* __restrict__ bih, const float* __restrict__ bhh,
                    const float* __restrict__ b1, const float* __restrict__ b2,
                    const float* __restrict__ lmg, const float* __restrict__ lmb,
                    const float* __restrict__ lsg, const float* __restrict__ lsb,
                    const float* __restrict__ b1o, const float* __restrict__ b2o,
                    float* __restrict__ outp, int last) {
  __shared__ float swih[8*384];            // 12 KB weight stage
  __shared__ float swhh[8*384];            // 12 KB
  __shared__ float s1s[128], s2s[128], mus[128];
  __shared__ float ps[6*256];
  __shared__ float hs[128];
  __shared__ float m1[128];
  __shared__ float sv[256];
  __shared__ float sn[256];
  __shared__ float tmp[128];
  __shared__ float red[8];
  int r = blockIdx.x, t = threadIdx.x, tt = t & 127, th = t >> 7;
  float gsum = g_gsum[r];
  if (t < 128) {
    float inv = 1.f/gsum;
    s1s[t] = g_accV[r*DD+t]*inv;
    s2s[t] = g_accV2[r*DD+t]*inv;
    mus[t] = g_mus[r*DD+t];
  }
  __syncthreads();
  // GRU gates: 16 chunks of 8 c-rows, register double-buffered staging
  {
    const float4* giT = (const float4*)g_WihT;
    const float4* ghT = (const float4*)g_WhhT;
    float4 ri[3], rh[3];
    #pragma unroll
    for (int rep=0;rep<3;++rep) { ri[rep]=giT[rep*256+t]; rh[rep]=ghT[rep*256+t]; }
    float gir=0,giz=0,gin=0,ghr=0,ghz=0,ghn=0;
    for (int ch=0; ch<16; ++ch) {
      __syncthreads();
      #pragma unroll
      for (int rep=0;rep<3;++rep) {
        ((float4*)swih)[rep*256+t]=ri[rep];
        ((float4*)swhh)[rep*256+t]=rh[rep];
      }
      __syncthreads();
      if (ch<15) {
        #pragma unroll
        for (int rep=0;rep<3;++rep) {
          ri[rep]=giT[(ch+1)*768+rep*256+t];
          rh[rep]=ghT[(ch+1)*768+rep*256+t];
        }
      }
      int cl0 = th*4;
      #pragma unroll
      for (int ci=0; ci<4; ++ci) {
        int cl = cl0 + ci, c = ch*8 + cl;
        float xv = s1s[c], hv = mus[c];
        const float* wi = &swih[cl*384];
        const float* wh = &swhh[cl*384];
        gir = fmaf(xv, wi[tt],     gir);  ghr = fmaf(hv, wh[tt],     ghr);
        giz = fmaf(xv, wi[128+tt], giz);  ghz = fmaf(hv, wh[128+tt], ghz);
        gin = fmaf(xv, wi[256+tt], gin);  ghn = fmaf(hv, wh[256+tt], ghn);
      }
    }
    ps[t]=gir; ps[256+t]=giz; ps[512+t]=gin;
    ps[768+t]=ghr; ps[1024+t]=ghz; ps[1280+t]=ghn;
  }
  __syncthreads();
  float upd1 = 0.f;
  if (t < 128) {
    float Gir = ps[t]+ps[t+128]       + bih[t];
    float Giz = ps[256+t]+ps[384+t]   + bih[128+t];
    float Gin = ps[512+t]+ps[640+t]   + bih[256+t];
    float Ghr = ps[768+t]+ps[896+t]   + bhh[t];
    float Ghz = ps[1024+t]+ps[1152+t] + bhh[128+t];
    float Ghn = ps[1280+t]+ps[1408+t] + bhh[256+t];
    float rg = 1.f/(1.f+expf(-(Gir+Ghr)));
    float zg = 1.f/(1.f+expf(-(Giz+Ghz)));
    float ng = tanhf(Gin + rg*Ghn);
    upd1 = (1.f-zg)*ng + zg*mus[t];
  }
  __syncthreads();
  // LN(upd1) over 128 (inactive threads contribute 0)
  {
    float v = (t<128) ? upd1 : 0.f;
    float m = blkSum8(v, red, t) * (1.f/128.f);
    float dv = (t<128) ? (upd1 - m) : 0.f;
    float var = blkSum8(dv*dv, red, t) * (1.f/128.f);
    float rs = rsqrtf(var + 1e-5f);
    if (t<128) hs[t] = dv*rs*lmg[t] + lmb[t];
  }
  __syncthreads();
  // MLP1: split c over halves
  {
    float a = 0.f;
    int c0 = th*64;
    #pragma unroll 16
    for (int c=c0; c<c0+64; ++c) a = fmaf(hs[c], g_W1muT[c*HH+tt], a);
    ps[t] = a;
  }
  __syncthreads();
  if (t < 128) m1[t] = fmaxf(ps[t]+ps[t+128]+b1[t], 0.f);
  __syncthreads();
  // MLP2: split j over halves
  {
    float a = 0.f;
    int j0 = th*64;
    #pragma unroll 16
    for (int j=j0; j<j0+64; ++j) a = fmaf(m1[j], g_W2muT[j*DD+tt], a);
    ps[t] = a;
  }
  __syncthreads();
  if (t < 128) {
    float out = upd1 + b2[t] + ps[t] + ps[t+128];
    float ls = 0.5f*logf(s2s[t] - 2.f*out*s1s[t] + out*out + EPSV);
    sv[t] = out;
    sv[128+t] = ls;
    if (t==0) g_pi[r] = gsum;
  }
  __syncthreads();
  if (!last) {
    qphase(r, sv, sn, tmp, red, lsg, lsb, t);
  } else {
    // final output MLP: h = relu(sv @ W1o^T + b1o), out = h @ W2o^T + b2o
    float a = b1o[t];
    #pragma unroll 16
    for (int c=0;c<256;++c) a = fmaf(sv[c], g_W1oT[c*256+t], a);
    sn[t] = fmaxf(a, 0.f);
    __syncthreads();
    if (t < 128) {
      float o = b2o[t];
      #pragma unroll 16
      for (int c=0;c<256;++c) o = fmaf(sn[c], g_W2oT[c*DD+t], o);
      outp[r*DD+t] = o;
    }
  }
}

extern "C" void kernel_launch(void* const* d_in, const int* in_sizes, int n_in,
                              void* d_out, int out_size) {
  const float* inputs  = (const float*)d_in[0];
  const float* noise   = (const float*)d_in[1];
  const float* smu     = (const float*)d_in[2];
  const float* slsig   = (const float*)d_in[3];
  const float* Wq      = (const float*)d_in[4];
  const float* Wk      = (const float*)d_in[5];
  const float* Wih     = (const float*)d_in[6];
  const float* Whh     = (const float*)d_in[7];
  const float* bih     = (const float*)d_in[8];
  const float* bhh     = (const float*)d_in[9];
  const float* W1mu    = (const float*)d_in[10];
  const float* b1mu    = (const float*)d_in[11];
  const float* W2mu    = (const float*)d_in[12];
  const float* b2mu    = (const float*)d_in[13];
  const float* ln_in_g = (const float*)d_in[14];
  const float* ln_in_b = (const float*)d_in[15];
  const float* lsg     = (const float*)d_in[16];
  const float* lsb     = (const float*)d_in[17];
  const float* lmg     = (const float*)d_in[18];
  const float* lmb     = (const float*)d_in[19];
  const float* W1o     = (const float*)d_in[20];
  const float* b1o     = (const float*)d_in[21];
  const float* W2o     = (const float*)d_in[22];
  const float* b2o     = (const float*)d_in[23];
  float* out = (float*)d_out;

  kInitT<<<192, 256>>>(noise, smu, slsig, lsg, lsb,
                       Wq, Wk, Wih, Whh, W1mu, W2mu, W1o, W2o);
  kA<<<(BB*NN)/64, 256>>>(inputs, ln_in_g, ln_in_b);
  for (int it=0; it<4; ++it) {
    kP<<<dim3(BB, NN/CH), 256>>>();
    kUQ<<<RWS, 256>>>(bih, bhh, b1mu, b2mu, lmg, lmb, lsg, lsb,
                      b1o, b2o, out, it==3 ? 1 : 0);
  }
}

// round 17
// speedup vs baseline: 1.1765x; 1.1640x over previous
#include <cuda_runtime.h>
#include <math.h>

#define BB   16
#define NN   2048
#define DD   128
#define NSL  8
#define HH   128
#define RWS  (BB*NSL)            // 128 slot rows
#define EPSV 1e-8f
#define CH   64                  // n-rows per kP chunk
#define KSTR 33                  // float4 stride for ks rows

// ---------------- scratch (__device__ globals: allocation-free) ----------------
__device__ float g_k[BB*NN*DD];          // 16 MB, k == v
__device__ float g_mus[RWS*DD];          // mu_s (GRU hidden)
__device__ float g_wa[RWS*DD];           // inv_var
__device__ float g_wb[RWS*DD];           // -2*inv*qmu
__device__ float g_wc[RWS];              // sum inv*qmu^2
__device__ float g_pi[RWS];
__device__ float g_gsum[RWS];
__device__ float g_accV[RWS*DD];
__device__ float g_accV2[RWS*DD];

// transposed weights
__device__ float g_WkT[DD*DD];           // [kk][c]
__device__ float g_WqT[DD*DD];           // [c][d]
__device__ float g_WihT[DD*3*DD];        // [c][j]
__device__ float g_WhhT[DD*3*DD];
__device__ float g_W1muT[DD*HH];         // [c][j]
__device__ float g_W2muT[HH*DD];         // [j][d]
__device__ float g_W1oT[2*DD*2*HH];      // [c][j]
__device__ float g_W2oT[2*HH*DD];        // [c][d]

// ---------------- kT: one-time weight transposes ----------------
__global__ void kT(const float* __restrict__ Wk, const float* __restrict__ Wq,
                   const float* __restrict__ Wih, const float* __restrict__ Whh,
                   const float* __restrict__ W1mu, const float* __restrict__ W2mu,
                   const float* __restrict__ W1o, const float* __restrict__ W2o) {
  int tid = blockIdx.x*blockDim.x + threadIdx.x;
  int stride = gridDim.x*blockDim.x;
  for (int i=tid;i<DD*DD;i+=stride){int c=i>>7,kk=i&127; g_WkT[kk*DD+c]=Wk[i];}
  for (int i=tid;i<DD*DD;i+=stride){int d=i>>7,c=i&127;  g_WqT[c*DD+d]=Wq[i];}
  for (int i=tid;i<3*DD*DD;i+=stride){int j=i>>7,c=i&127; g_WihT[c*384+j]=Wih[i]; g_WhhT[c*384+j]=Whh[i];}
  for (int i=tid;i<HH*DD;i+=stride){int j=i>>7,c=i&127;  g_W1muT[c*HH+j]=W1mu[i];}
  for (int i=tid;i<DD*HH;i+=stride){int d=i>>7,j=i&127;  g_W2muT[j*DD+d]=W2mu[i];}
  for (int i=tid;i<2*HH*2*DD;i+=stride){int j=i>>8,c=i&255; g_W1oT[c*256+j]=W1o[i];}
  for (int i=tid;i<DD*2*HH;i+=stride){int d=i>>8,c=i&255; g_W2oT[c*DD+d]=W2o[i];}
}

// ---------------- kA: fused LayerNorm + k = xn @ Wk^T ----------------
__global__ void kA(const float* __restrict__ inp,
                   const float* __restrict__ lng, const float* __restrict__ lnb) {
  __shared__ float xs[64*DD];
  __shared__ float wt[16*DD];
  const int tid = threadIdx.x;
  const int r0blk = blockIdx.x*64;
  for (int idx=tid; idx<64*DD; idx+=256) xs[idx] = inp[(long)r0blk*DD + idx];
  __syncthreads();
  {
    int w = tid>>5, lane = tid&31;
    for (int r=w*8; r<w*8+8; ++r) {
      float x0=xs[r*DD+lane],    x1=xs[r*DD+lane+32];
      float x2=xs[r*DD+lane+64], x3=xs[r*DD+lane+96];
      float s = x0+x1+x2+x3;
      #pragma unroll
      for (int o=16;o;o>>=1) s += __shfl_xor_sync(0xffffffffu,s,o);
      float m = s*(1.f/128.f);
      float d0=x0-m,d1=x1-m,d2=x2-m,d3=x3-m;
      float s2 = d0*d0+d1*d1+d2*d2+d3*d3;
      #pragma unroll
      for (int o=16;o;o>>=1) s2 += __shfl_xor_sync(0xffffffffu,s2,o);
      float rs = rsqrtf(s2*(1.f/128.f)+1e-5f);
      xs[r*DD+lane]    = d0*rs*lng[lane]    + lnb[lane];
      xs[r*DD+lane+32] = d1*rs*lng[lane+32] + lnb[lane+32];
      xs[r*DD+lane+64] = d2*rs*lng[lane+64] + lnb[lane+64];
      xs[r*DD+lane+96] = d3*rs*lng[lane+96] + lnb[lane+96];
    }
  }
  const int cg = tid&31, rg = tid>>5;
  const int c0 = cg*4, r0 = rg*8;
  float4 acc[8];
  #pragma unroll
  for (int r=0;r<8;++r) acc[r] = make_float4(0.f,0.f,0.f,0.f);
  for (int kt=0; kt<8; ++kt) {
    __syncthreads();
    for (int i=tid; i<16*DD; i+=256) wt[i] = g_WkT[kt*16*DD + i];
    __syncthreads();
    #pragma unroll 4
    for (int kk=0;kk<16;++kk) {
      float4 wv = *(const float4*)&wt[kk*DD+c0];
      int kg = kt*16 + kk;
      #pragma unroll
      for (int r=0;r<8;++r) {
        float xv = xs[(r0+r)*DD+kg];
        acc[r].x = fmaf(xv,wv.x,acc[r].x);
        acc[r].y = fmaf(xv,wv.y,acc[r].y);
        acc[r].z = fmaf(xv,wv.z,acc[r].z);
        acc[r].w = fmaf(xv,wv.w,acc[r].w);
      }
    }
  }
  #pragma unroll
  for (int r=0;r<8;++r)
    *(float4*)&g_k[(long)(r0blk + r0 + r)*DD + c0] = acc[r];
}

// ---------------- generic block reduce (NW warps) ----------------
template<int NW>
__device__ __forceinline__ float blkSumN(float v, float* red, int tid) {
  int lane = tid&31, w = tid>>5;
  #pragma unroll
  for (int o=16;o;o>>=1) v += __shfl_xor_sync(0xffffffffu,v,o);
  if (lane==0) red[w] = v;
  __syncthreads();
  float tot = 0.f;
  #pragma unroll
  for (int i=0;i<NW;++i) tot += red[i];
  __syncthreads();
  return tot;
}

// ---------------- kInit: slot init + pi + first Q-phase (256 threads) ----------
__global__ void kInit(const float* __restrict__ noise, const float* __restrict__ smu,
                      const float* __restrict__ slsig,
                      const float* __restrict__ lsg, const float* __restrict__ lsb) {
  __shared__ float sv[256];
  __shared__ float sn[256];
  __shared__ float tmp[128];
  __shared__ float red[8];
  int r = blockIdx.x, t = threadIdx.x;
  sv[t] = smu[t] + expf(slsig[t])*noise[r*256+t];
  if (t==0) g_pi[r] = 1.f/(float)NSL;
  __syncthreads();
  float x = sv[t];
  float m = blkSumN<8>(x, red, t) * (1.f/256.f);
  float dv = x - m;
  float var = blkSumN<8>(dv*dv, red, t) * (1.f/256.f);
  float rs = rsqrtf(var + 1e-5f);
  sn[t] = dv*rs*lsg[t] + lsb[t];
  __syncthreads();
  int idx = t & 127;
  const float* s = (t < 128) ? &sn[0] : &sn[128];
  float acc = 0.f;
  #pragma unroll 16
  for (int c=0;c<128;++c) acc = fmaf(s[c], g_WqT[c*DD+idx], acc);
  if (t >= 128) {
    float inv = expf(-2.f*acc);
    g_wa[r*DD+idx] = inv;
    tmp[idx] = inv;
  }
  __syncthreads();
  float cpart = 0.f;
  if (t < 128) {
    float inv = tmp[t];
    g_wb[r*DD+t] = -2.f*inv*acc;
    g_mus[r*DD+t] = sn[t];
    g_accV[r*DD+t] = 0.f;
    g_accV2[r*DD+t] = 0.f;
    cpart = inv*acc*acc;
  }
  float C = blkSumN<8>(cpart, red, t);
  if (t==0) { g_wc[r] = C; g_gsum[r] = 0.f; }
}

// ---------------- kP: fused dots/gamma/moment pass (R11 version) ---------------
__global__ void __launch_bounds__(256, 4) kP() {
  __shared__ float4 ks4[CH*KSTR];
  __shared__ float4 wa4[8*KSTR];
  __shared__ float4 wb4[8*KSTR];
  __shared__ float pd[8*64];
  __shared__ float gm[CH*8];
  __shared__ float sC[8], sPi[8];
  int b = blockIdx.x, chunk = blockIdx.y;
  int tid = threadIdx.x, lane = tid&31, w = tid>>5;
  {
    int s = tid>>5, i = tid&31;
    wa4[s*KSTR+i] = ((const float4*)&g_wa[(b*8+s)*DD])[i];
    wb4[s*KSTR+i] = ((const float4*)&g_wb[(b*8+s)*DD])[i];
  }
  if (tid<8) { sC[tid] = g_wc[b*8+tid]; sPi[tid] = g_pi[b*8+tid]; }
  {
    const float4* src = (const float4*)&g_k[(long)b*NN*DD + (long)chunk*CH*DD];
    #pragma unroll
    for (int rep=0; rep<8; ++rep) {
      int i = rep*256 + tid;
      ks4[(i>>5)*KSTR + (i&31)] = src[i];
    }
  }
  __syncthreads();
  {
    int n = tid&63, sg = tid>>6;
    int s0 = sg*2, s1 = sg*2+1;
    const float4* kr  = &ks4[n*KSTR];
    const float4* wa0 = &wa4[s0*KSTR];
    const float4* wb0 = &wb4[s0*KSTR];
    const float4* wa1 = &wa4[s1*KSTR];
    const float4* wb1 = &wb4[s1*KSTR];
    float d0 = 0.f, d1 = 0.f;
    #pragma unroll 8
    for (int i=0;i<32;++i) {
      float4 k4 = kr[i];
      float4 a4 = wa0[i], b4 = wb0[i];
      float p = fmaf(a4.x,k4.x,b4.x)*k4.x;
      p = fmaf(fmaf(a4.y,k4.y,b4.y), k4.y, p);
      p = fmaf(fmaf(a4.z,k4.z,b4.z), k4.z, p);
      p = fmaf(fmaf(a4.w,k4.w,b4.w), k4.w, p);
      d0 += p;
      float4 a5 = wa1[i], b5 = wb1[i];
      float q = fmaf(a5.x,k4.x,b5.x)*k4.x;
      q = fmaf(fmaf(a5.y,k4.y,b5.y), k4.y, q);
      q = fmaf(fmaf(a5.z,k4.z,b5.z), k4.z, q);
      q = fmaf(fmaf(a5.w,k4.w,b5.w), k4.w, q);
      d1 += q;
    }
    pd[s0*64+n] = d0;
    pd[s1*64+n] = d1;
  }
  __syncthreads();
  if (tid < 64) {
    int n = tid;
    float e[8], ssum = 0.f;
    #pragma unroll
    for (int s=0;s<8;++s) {
      float dot = pd[s*64+n] + sC[s];
      e[s] = (expf(-dot) + EPSV) * sPi[s];
      ssum += e[s];
    }
    float inv = 1.f/ssum;
    #pragma unroll
    for (int s=0;s<8;++s) gm[n*8+s] = e[s]*inv;
  }
  __syncthreads();
  {
    int sp = w & 3, nh = w >> 2;
    int s0 = sp*2, s1 = sp*2+1;
    float4 aV0 = make_float4(0,0,0,0), a20 = make_float4(0,0,0,0);
    float4 aV1 = make_float4(0,0,0,0), a21 = make_float4(0,0,0,0);
    float gs0 = 0.f, gs1 = 0.f;
    #pragma unroll 4
    for (int ni=0; ni<32; ++ni) {
      int n = nh*32 + ni;
      float4 k4 = ks4[n*KSTR+lane];
      float2 g2 = *(const float2*)&gm[n*8 + s0];
      float g0 = g2.x, g1 = g2.y;
      gs0 += g0; gs1 += g1;
      float sx = k4.x*k4.x, sy = k4.y*k4.y, sz = k4.z*k4.z, sw = k4.w*k4.w;
      aV0.x = fmaf(g0,k4.x,aV0.x); aV0.y = fmaf(g0,k4.y,aV0.y);
      aV0.z = fmaf(g0,k4.z,aV0.z); aV0.w = fmaf(g0,k4.w,aV0.w);
      a20.x = fmaf(g0,sx,a20.x); a20.y = fmaf(g0,sy,a20.y);
      a20.z = fmaf(g0,sz,a20.z); a20.w = fmaf(g0,sw,a20.w);
      aV1.x = fmaf(g1,k4.x,aV1.x); aV1.y = fmaf(g1,k4.y,aV1.y);
      aV1.z = fmaf(g1,k4.z,aV1.z); aV1.w = fmaf(g1,k4.w,aV1.w);
      a21.x = fmaf(g1,sx,a21.x); a21.y = fmaf(g1,sy,a21.y);
      a21.z = fmaf(g1,sz,a21.z); a21.w = fmaf(g1,sw,a21.w);
    }
    float* pV0 = &g_accV [(b*8+s0)*DD + lane*4];
    float* p20 = &g_accV2[(b*8+s0)*DD + lane*4];
    float* pV1 = &g_accV [(b*8+s1)*DD + lane*4];
    float* p21 = &g_accV2[(b*8+s1)*DD + lane*4];
    atomicAdd(pV0+0,aV0.x); atomicAdd(pV0+1,aV0.y);
    atomicAdd(pV0+2,aV0.z); atomicAdd(pV0+3,aV0.w);
    atomicAdd(p20+0,a20.x); atomicAdd(p20+1,a20.y);
    atomicAdd(p20+2,a20.z); atomicAdd(p20+3,a20.w);
    atomicAdd(pV1+0,aV1.x); atomicAdd(pV1+1,aV1.y);
    atomicAdd(pV1+2,aV1.z); atomicAdd(pV1+3,aV1.w);
    atomicAdd(p21+0,a21.x); atomicAdd(p21+1,a21.y);
    atomicAdd(p21+2,a21.z); atomicAdd(p21+3,a21.w);
    if (lane==0) { atomicAdd(&g_gsum[b*8+s0], gs0); atomicAdd(&g_gsum[b*8+s1], gs1); }
  }
}

// ---------------- kUQ: 768 threads, one thread per GRU gate output -------------
// 128 blocks (slot rows); direct coalesced weight reads, no staging
__global__ void kUQ(const float* __restrict__ bih, const float* __restrict__ bhh,
                    const float* __restrict__ b1, const float* __restrict__ b2,
                    const float* __restrict__ lmg, const float* __restrict__ lmb,
                    const float* __restrict__ lsg, const float* __restrict__ lsb,
                    const float* __restrict__ b1o, const float* __restrict__ b2o,
                    float* __restrict__ outp, int last) {
  __shared__ float s1s[128], s2s[128], mus[128];
  __shared__ float gi[384], gh[384];
  __shared__ float ups[128], hs[128], m1[128];
  __shared__ float ps[512];
  __shared__ float sv[256], sn[256];
  __shared__ float tmp[128];
  __shared__ float red[24];
  int r = blockIdx.x, t = threadIdx.x;
  float gsum = g_gsum[r];
  if (t < 128) {
    float inv = 1.f/gsum;
    s1s[t] = g_accV[r*DD+t]*inv;
    s2s[t] = g_accV2[r*DD+t]*inv;
    mus[t] = g_mus[r*DD+t];
  }
  __syncthreads();
  // GRU gates: thread = gate output (384 ih + 384 hh), full 128-c contraction
  {
    int o = (t < 384) ? t : t - 384;
    const float* W = (t < 384) ? g_WihT : g_WhhT;
    const float* x = (t < 384) ? s1s : mus;
    float a = 0.f;
    #pragma unroll 16
    for (int c=0;c<128;++c) a = fmaf(x[c], W[c*384+o], a);
    if (t < 384) gi[o] = a; else gh[o] = a;
  }
  __syncthreads();
  if (t < 128) {
    float Gir = gi[t]     + bih[t];
    float Giz = gi[128+t] + bih[128+t];
    float Gin = gi[256+t] + bih[256+t];
    float Ghr = gh[t]     + bhh[t];
    float Ghz = gh[128+t] + bhh[128+t];
    float Ghn = gh[256+t] + bhh[256+t];
    float rg = 1.f/(1.f+expf(-(Gir+Ghr)));
    float zg = 1.f/(1.f+expf(-(Giz+Ghz)));
    float ng = tanhf(Gin + rg*Ghn);
    ups[t] = (1.f-zg)*ng + zg*mus[t];
  }
  __syncthreads();
  // LN(ups) over 128
  {
    float v = (t<128) ? ups[t] : 0.f;
    float m = blkSumN<24>(v, red, t) * (1.f/128.f);
    float dv = (t<128) ? (ups[t] - m) : 0.f;
    float var = blkSumN<24>(dv*dv, red, t) * (1.f/128.f);
    float rs = rsqrtf(var + 1e-5f);
    if (t<128) hs[t] = dv*rs*lmg[t] + lmb[t];
  }
  __syncthreads();
  // MLP1: t<512 -> (j = t&127, q = t>>7), c in [q*32, q*32+32)
  if (t < 512) {
    int j = t&127, q = t>>7;
    float a = 0.f;
    int c0 = q*32;
    #pragma unroll 8
    for (int c=c0; c<c0+32; ++c) a = fmaf(hs[c], g_W1muT[c*HH+j], a);
    ps[q*128+j] = a;
  }
  __syncthreads();
  if (t < 128) m1[t] = fmaxf(ps[t]+ps[128+t]+ps[256+t]+ps[384+t]+b1[t], 0.f);
  __syncthreads();
  // MLP2: t<512 -> (d = t&127, q = t>>7), j in [q*32, q*32+32)
  if (t < 512) {
    int d = t&127, q = t>>7;
    float a = 0.f;
    int j0 = q*32;
    #pragma unroll 8
    for (int j=j0; j<j0+32; ++j) a = fmaf(m1[j], g_W2muT[j*DD+d], a);
    ps[q*128+d] = a;
  }
  __syncthreads();
  if (t < 128) {
    float out = ups[t] + b2[t] + ps[t]+ps[128+t]+ps[256+t]+ps[384+t];
    float ls = 0.5f*logf(s2s[t] - 2.f*out*s1s[t] + out*out + EPSV);
    sv[t] = out;
    sv[128+t] = ls;
    if (t==0) g_pi[r] = gsum;
  }
  __syncthreads();
  if (!last) {
    // Q-phase: LN over 256, then Wq with 2-way c-split
    {
      float v = (t<256) ? sv[t] : 0.f;
      float m = blkSumN<24>(v, red, t) * (1.f/256.f);
      float dv = (t<256) ? (sv[t] - m) : 0.f;
      float var = blkSumN<24>(dv*dv, red, t) * (1.f/256.f);
      float rs = rsqrtf(var + 1e-5f);
      if (t<256) sn[t] = dv*rs*lsg[t] + lsb[t];
    }
    __syncthreads();
    if (t < 512) {
      int idx2 = t&255, h = t>>8;
      int idx = idx2 & 127;
      const float* s = (idx2 < 128) ? &sn[0] : &sn[128];
      float a = 0.f;
      int c0 = h*64;
      #pragma unroll 16
      for (int c=c0; c<c0+64; ++c) a = fmaf(s[c], g_WqT[c*DD+idx], a);
      ps[h*256+idx2] = a;
    }
    __syncthreads();
    if (t >= 128 && t < 256) {
      int idx = t-128;
      float acc = ps[t] + ps[256+t];
      float inv = expf(-2.f*acc);
      g_wa[r*DD+idx] = inv;
      tmp[idx] = inv;
    }
    __syncthreads();
    float cpart = 0.f;
    if (t < 128) {
      float acc = ps[t] + ps[256+t];   // qmu
      float inv = tmp[t];
      g_wb[r*DD+t] = -2.f*inv*acc;
      g_mus[r*DD+t] = sn[t];
      g_accV[r*DD+t] = 0.f;
      g_accV2[r*DD+t] = 0.f;
      cpart = inv*acc*acc;
    }
    float C = blkSumN<24>(cpart, red, t);
    if (t==0) { g_wc[r] = C; g_gsum[r] = 0.f; }
  } else {
    // final MLP: h = relu(sv @ W1o^T + b1o) [256 out x 256 c], 2-way c-split
    if (t < 512) {
      int o = t&255, h = t>>8;
      float a = 0.f;
      int c0 = h*128;
      #pragma unroll 16
      for (int c=c0; c<c0+128; ++c) a = fmaf(sv[c], g_W1oT[c*256+o], a);
      ps[h*256+o] = a;
    }
    __syncthreads();
    if (t < 256) sn[t] = fmaxf(ps[t] + ps[256+t] + b1o[t], 0.f);
    __syncthreads();
    // out = sn @ W2o^T + b2o [128 out x 256 c], 4-way c-split
    if (t < 512) {
      int d = t&127, q = t>>7;
      float a = 0.f;
      int c0 = q*64;
      #pragma unroll 16
      for (int c=c0; c<c0+64; ++c) a = fmaf(sn[c], g_W2oT[c*DD+d], a);
      ps[q*128+d] = a;
    }
    __syncthreads();
    if (t < 128)
      outp[r*DD+t] = ps[t]+ps[128+t]+ps[256+t]+ps[384+t] + b2o[t];
  }
}

extern "C" void kernel_launch(void* const* d_in, const int* in_sizes, int n_in,
                              void* d_out, int out_size) {
  const float* inputs  = (const float*)d_in[0];
  const float* noise   = (const float*)d_in[1];
  const float* smu     = (const float*)d_in[2];
  const float* slsig   = (const float*)d_in[3];
  const float* Wq      = (const float*)d_in[4];
  const float* Wk      = (const float*)d_in[5];
  const float* Wih     = (const float*)d_in[6];
  const float* Whh     = (const float*)d_in[7];
  const float* bih     = (const float*)d_in[8];
  const float* bhh     = (const float*)d_in[9];
  const float* W1mu    = (const float*)d_in[10];
  const float* b1mu    = (const float*)d_in[11];
  const float* W2mu    = (const float*)d_in[12];
  const float* b2mu    = (const float*)d_in[13];
  const float* ln_in_g = (const float*)d_in[14];
  const float* ln_in_b = (const float*)d_in[15];
  const float* lsg     = (const float*)d_in[16];
  const float* lsb     = (const float*)d_in[17];
  const float* lmg     = (const float*)d_in[18];
  const float* lmb     = (const float*)d_in[19];
  const float* W1o     = (const float*)d_in[20];
  const float* b1o     = (const float*)d_in[21];
  const float* W2o     = (const float*)d_in[22];
  const float* b2o     = (const float*)d_in[23];
  float* out = (float*)d_out;

  kT<<<64, 256>>>(Wk, Wq, Wih, Whh, W1mu, W2mu, W1o, W2o);
  kA<<<(BB*NN)/64, 256>>>(inputs, ln_in_g, ln_in_b);
  kInit<<<RWS, 256>>>(noise, smu, slsig, lsg, lsb);
  for (int it=0; it<4; ++it) {
    kP<<<dim3(BB, NN/CH), 256>>>();
    kUQ<<<RWS, 768>>>(bih, bhh, b1mu, b2mu, lmg, lmb, lsg, lsb,
                      b1o, b2o, out, it==3 ? 1 : 0);
  }
}